// round 15
// baseline (speedup 1.0000x reference)
// RBF regression out[B,F] = exp(-||z-x||^2/2) @ alpha.
// R15: hybrid-precision Gram GEMM at 2/3 the tensor work of R12:
//   hi  pass: zh*xh in fp16 mma (m16n8k16, f32 accum), -hz in accumulator init
//   mid pass: zl*xh + zh*xl as ONE int8 K=128 concat mma (m16n8k32, s32 accum,
//             exact), A=[s8(zl*2^15)|s8(zh*2^4)], B=[s8(xh*2^4)|s8(xl*2^15)],
//             folded with scale 2^-19.
// z pre-scaled by log2e so epilogue is FADD + ex2.approx; K@alpha second GEMM
// in registers (fma.rn.f32x2); 2-stage cp.async; deterministic slabs + reduce.
#include <cuda_runtime.h>
#include <cuda_fp16.h>
#include <cstdint>

#define DD 64
#define FF 16
#define MT 128
#define NTL 128
#define NCH 37
#define MBLK 16
#define NSLAB (NCH * 2)
#define MAXB 2048
#define MAXN 100096
#define LOG2E 1.4426950408889634f
#define SCMID 0x1p-19f

typedef unsigned long long ull;

__device__ __align__(16) __half  g_zh16[MAXB * DD];
__device__ __align__(16) uint8_t g_z8[(size_t)MAXB * 128];    // [zl8*2^15 | zh8*2^4]
__device__ __align__(16) __half  g_xh16[(size_t)MAXN * DD];
__device__ __align__(16) uint8_t g_x8[(size_t)MAXN * 128];    // [xh8*2^4 | xl8*2^15]
__device__ float g_hz[MAXB];
__device__ __align__(16) float g_hx[MAXN];
__device__ __align__(16) float g_part[(size_t)NSLAB * MAXB * FF];

// smem layout (bytes)
#define SM_ZH 0                // 16KB zh16 tile (128 rows x 128B)
#define SM_Z8 16384            // 16KB z8 tile
#define SM_X  32768            // per buf 32KB: xh16 +0, x8 +16384 (x2 bufs)
#define SM_AL 98304            // per buf 10240 (128 rows x 80B padded)
#define SM_HX 118784           // per buf 512
#define SM_TOT 119808

static __device__ __forceinline__ uint32_t smem_u32(const void* p) {
    uint32_t a;
    asm("{ .reg .u64 t; cvta.to.shared.u64 t, %1; cvt.u32.u64 %0, t; }"
        : "=r"(a) : "l"(p));
    return a;
}
static __device__ __forceinline__ uint32_t swz(uint32_t o) {
    return o ^ ((o >> 3) & 0x70);
}
static __device__ __forceinline__ float ex2f(float x) {
    float y;
    asm("ex2.approx.ftz.f32 %0, %1;" : "=f"(y) : "f"(x));
    return y;
}
static __device__ __forceinline__ ull pack2(float e) {
    ull r;
    asm("mov.b64 %0, {%1, %1};" : "=l"(r) : "f"(e));
    return r;
}
static __device__ __forceinline__ void fma2(ull& acc, ull a, ull b) {
    asm("fma.rn.f32x2 %0, %1, %2, %0;" : "+l"(acc) : "l"(a), "l"(b));
}
static __device__ __forceinline__ void ldm4(uint32_t a, uint32_t r[4]) {
    asm volatile("ldmatrix.sync.aligned.m8n8.x4.shared.b16 {%0,%1,%2,%3}, [%4];"
                 : "=r"(r[0]), "=r"(r[1]), "=r"(r[2]), "=r"(r[3]) : "r"(a));
}
static __device__ __forceinline__ void mma_f16(float c[4], const uint32_t a[4],
                                               uint32_t b0, uint32_t b1) {
    asm volatile(
        "mma.sync.aligned.m16n8k16.row.col.f32.f16.f16.f32 "
        "{%0,%1,%2,%3}, {%4,%5,%6,%7}, {%8,%9}, {%0,%1,%2,%3};"
        : "+f"(c[0]), "+f"(c[1]), "+f"(c[2]), "+f"(c[3])
        : "r"(a[0]), "r"(a[1]), "r"(a[2]), "r"(a[3]), "r"(b0), "r"(b1));
}
static __device__ __forceinline__ void mma_s8(int c[4], const uint32_t a[4],
                                              uint32_t b0, uint32_t b1) {
    asm volatile(
        "mma.sync.aligned.m16n8k32.row.col.s32.s8.s8.s32 "
        "{%0,%1,%2,%3}, {%4,%5,%6,%7}, {%8,%9}, {%0,%1,%2,%3};"
        : "+r"(c[0]), "+r"(c[1]), "+r"(c[2]), "+r"(c[3])
        : "r"(a[0]), "r"(a[1]), "r"(a[2]), "r"(a[3]), "r"(b0), "r"(b1));
}
static __device__ __forceinline__ void cpa16(uint32_t dst, const void* src, int sz) {
    asm volatile("cp.async.cg.shared.global [%0], [%1], 16, %2;"
                 :: "r"(dst), "l"(src), "r"(sz) : "memory");
}
#define CP_COMMIT() asm volatile("cp.async.commit_group;" ::: "memory")
#define CP_WAIT1()  asm volatile("cp.async.wait_group 1;" ::: "memory")
#define CP_WAIT0()  asm volatile("cp.async.wait_group 0;" ::: "memory")

static __device__ __forceinline__ int sat8(float v) {
    int q = __float2int_rn(v);
    return max(-127, min(127, q));
}
static __device__ __forceinline__ uint32_t pack8(int a, int b, int c, int d) {
    return (uint32_t)(a & 255) | ((uint32_t)(b & 255) << 8) |
           ((uint32_t)(c & 255) << 16) | ((uint32_t)(d & 255) << 24);
}

// ---------- prep: fp16 hi + s8 residual encodings + half-norms ----------
__global__ void prep_split(const float* __restrict__ z,
                           const float* __restrict__ x, int B, int N) {
    int i = blockIdx.x * blockDim.x + threadIdx.x;
    if (i < N) {
        const float4* p = reinterpret_cast<const float4*>(x + (size_t)i * DD);
        float s = 0.f;
#pragma unroll
        for (int q = 0; q < DD / 4; q++) {
            float4 v = p[q];
            s += v.x * v.x + v.y * v.y + v.z * v.z + v.w * v.w;
            float vv[4] = {v.x, v.y, v.z, v.w};
            __half h[4];
            int hq[4], lq[4];
#pragma unroll
            for (int e = 0; e < 4; e++) {
                h[e] = __float2half(vv[e]);
                float hf = __half2float(h[e]);
                hq[e] = sat8(hf * 16.0f);
                lq[e] = sat8((vv[e] - hf) * 32768.0f);
            }
            *reinterpret_cast<uint2*>(g_xh16 + (size_t)i * DD + q * 4) =
                *reinterpret_cast<uint2*>(h);
            // x8 row: bytes [0,64) = xh*2^4, [64,128) = xl*2^15
            *reinterpret_cast<uint32_t*>(g_x8 + (size_t)i * 128 + q * 4) =
                pack8(hq[0], hq[1], hq[2], hq[3]);
            *reinterpret_cast<uint32_t*>(g_x8 + (size_t)i * 128 + 64 + q * 4) =
                pack8(lq[0], lq[1], lq[2], lq[3]);
        }
        g_hx[i] = 0.5f * s * LOG2E;
    } else if (i < N + B) {
        int b = i - N;
        const float4* p = reinterpret_cast<const float4*>(z + (size_t)b * DD);
        float s = 0.f;
#pragma unroll
        for (int q = 0; q < DD / 4; q++) {
            float4 v = p[q];
            s += v.x * v.x + v.y * v.y + v.z * v.z + v.w * v.w;
            float vv[4] = {v.x * LOG2E, v.y * LOG2E, v.z * LOG2E, v.w * LOG2E};
            __half h[4];
            int hq[4], lq[4];
#pragma unroll
            for (int e = 0; e < 4; e++) {
                h[e] = __float2half(vv[e]);
                float hf = __half2float(h[e]);
                hq[e] = sat8(hf * 16.0f);
                lq[e] = sat8((vv[e] - hf) * 32768.0f);
            }
            *reinterpret_cast<uint2*>(g_zh16 + (size_t)b * DD + q * 4) =
                *reinterpret_cast<uint2*>(h);
            // z8 row: bytes [0,64) = zl*2^15, [64,128) = zh*2^4
            *reinterpret_cast<uint32_t*>(g_z8 + (size_t)b * 128 + q * 4) =
                pack8(lq[0], lq[1], lq[2], lq[3]);
            *reinterpret_cast<uint32_t*>(g_z8 + (size_t)b * 128 + 64 + q * 4) =
                pack8(hq[0], hq[1], hq[2], hq[3]);
        }
        g_hz[b] = 0.5f * s * LOG2E;
    }
}

// ---------- per-tile loads (cp.async) ----------
static __device__ __forceinline__ void load_tile(uint32_t su, const float* alpha,
                                                 int buf, int nb, int t, int N) {
    uint32_t xh_b = su + SM_X + buf * 32768;
    uint32_t x8_b = xh_b + 16384;
#pragma unroll
    for (int r4 = 0; r4 < 4; r4++) {
        int i = t + r4 * 256;
        int r = i >> 3, c = i & 7;
        int g = nb + r;
        int sz = g < N ? 16 : 0;
        int gg = g < N ? g : 0;
        cpa16(xh_b + swz(r * 128 + c * 16), g_xh16 + (size_t)gg * DD + c * 8, sz);
        cpa16(x8_b + swz(r * 128 + c * 16), g_x8 + (size_t)gg * 128 + c * 16, sz);
    }
    uint32_t al_b = su + SM_AL + buf * 10240;
#pragma unroll
    for (int r2 = 0; r2 < 2; r2++) {
        int i = t + r2 * 256;
        int n = i >> 2, c = i & 3;
        int g = nb + n;
        int sz = g < N ? 16 : 0;
        cpa16(al_b + n * 80 + c * 16,
              alpha + (size_t)(g < N ? g : 0) * FF + c * 4, sz);
    }
    if (t < 32) {
        int pos = nb + t * 4;
        int rem = N - pos;
        int sz = rem >= 4 ? 16 : (rem > 0 ? rem * 4 : 0);
        cpa16(su + SM_HX + buf * 512 + t * 16, g_hx + (pos < N ? pos : 0), sz);
    }
}

__global__ __launch_bounds__(256, 1) void rbf_main(
    const float* __restrict__ alpha, int N, int ntiles) {
    extern __shared__ char sm[];
    const uint32_t su = smem_u32(sm);
    const int t = threadIdx.x, lane = t & 31, wid = t >> 5;
    const int wm = wid & 3, wn = wid >> 2;
    const int chunk = blockIdx.x, mb = blockIdx.y * MT;
    const int tc = (ntiles - chunk + NCH - 1) / NCH;
    const int g8 = lane >> 2;

    // z tiles (once), SW128 swizzled: zh16 and z8
#pragma unroll
    for (int r4 = 0; r4 < 4; r4++) {
        int i = t + r4 * 256;
        int r = i >> 3, c = i & 7;
        *(uint4*)(sm + SM_ZH + swz(r * 128 + c * 16)) =
            *(const uint4*)(g_zh16 + (size_t)(mb + r) * DD + c * 8);
        *(uint4*)(sm + SM_Z8 + swz(r * 128 + c * 16)) =
            *(const uint4*)(g_z8 + (size_t)(mb + r) * 128 + c * 16);
    }

    float nhz[4];
#pragma unroll
    for (int mm = 0; mm < 4; mm++)
        nhz[mm] = -g_hz[mb + wm * 32 + (mm >> 1) * 16 + (mm & 1) * 8 + g8];

    // ldmatrix lane addressing (pure bit math; swizzle = XOR of lg<<4)
    const int lg = lane & 7, sel = lane >> 3;
    const uint32_t xr = (uint32_t)lg << 4;
    const uint32_t a_row = ((sel & 1) << 3) + lg;
    const uint32_t a_kx = (uint32_t)(sel >> 1) << 4;
    const uint32_t b_row = ((sel >> 1) << 3) + lg;
    const uint32_t b_kx = (uint32_t)(sel & 1) << 4;
    uint32_t abase16[2], abase8[2];
#pragma unroll
    for (int mi = 0; mi < 2; mi++) {
        uint32_t ro = (wm * 32 + mi * 16 + a_row) * 128;
        abase16[mi] = su + SM_ZH + ro;
        abase8[mi] = su + SM_Z8 + ro;
    }

    ull o[4][8];
#pragma unroll
    for (int mm = 0; mm < 4; mm++)
#pragma unroll
        for (int fp = 0; fp < 8; fp++) o[mm][fp] = 0ull;

    // 2-stage cp.async prologue
    load_tile(su, alpha, 0, chunk * NTL, t, N);
    CP_COMMIT();
    if (tc > 1) {
        load_tile(su, alpha, 1, (chunk + NCH) * NTL, t, N);
        CP_COMMIT();
    }

    for (int j = 0; j < tc; j++) {
        const int bi = j & 1;
        if (j + 1 < tc) CP_WAIT1(); else CP_WAIT0();
        __syncthreads();

        // ---- hi pass: zh16 * xh16 via fp16 mma, acc init = -hz ----
        float acc[2][8][4];
#pragma unroll
        for (int mi = 0; mi < 2; mi++)
#pragma unroll
            for (int ni = 0; ni < 8; ni++) {
                acc[mi][ni][0] = nhz[2 * mi];
                acc[mi][ni][1] = nhz[2 * mi];
                acc[mi][ni][2] = nhz[2 * mi + 1];
                acc[mi][ni][3] = nhz[2 * mi + 1];
            }
        const uint32_t xh_b = su + SM_X + bi * 32768;
        const uint32_t x8_b = xh_b + 16384;
        uint32_t bbase16[4], bbase8[4];
#pragma unroll
        for (int q = 0; q < 4; q++) {
            uint32_t ro = (wn * 64 + q * 16 + b_row) * 128;
            bbase16[q] = xh_b + ro;
            bbase8[q] = x8_b + ro;
        }
#pragma unroll
        for (int ks = 0; ks < 4; ks++) {
            const uint32_t kxa = ((uint32_t)(ks * 32) + a_kx) ^ xr;
            const uint32_t kxb = ((uint32_t)(ks * 32) + b_kx) ^ xr;
            uint32_t ah[2][4];
            ldm4(abase16[0] + kxa, ah[0]);
            ldm4(abase16[1] + kxa, ah[1]);
#pragma unroll
            for (int q = 0; q < 4; q++) {
                uint32_t bh4[4];
                ldm4(bbase16[q] + kxb, bh4);
#pragma unroll
                for (int h = 0; h < 2; h++) {
                    const int ni = 2 * q + h;
                    mma_f16(acc[0][ni], ah[0], bh4[2 * h], bh4[2 * h + 1]);
                    mma_f16(acc[1][ni], ah[1], bh4[2 * h], bh4[2 * h + 1]);
                }
            }
        }

        // ---- mid pass: (zl*xh + zh*xl) via one s8 K=128 concat mma ----
        uint32_t a8[2][4][4];
#pragma unroll
        for (int mi = 0; mi < 2; mi++)
#pragma unroll
            for (int kk = 0; kk < 4; kk++)
                ldm4(abase8[mi] + (((uint32_t)(kk * 32) + a_kx) ^ xr), a8[mi][kk]);
#pragma unroll
        for (int q = 0; q < 4; q++) {
            uint32_t b8[4][4];
#pragma unroll
            for (int kk = 0; kk < 4; kk++)
                ldm4(bbase8[q] + (((uint32_t)(kk * 32) + b_kx) ^ xr), b8[kk]);
#pragma unroll
            for (int h = 0; h < 2; h++) {
                const int ni = 2 * q + h;
#pragma unroll
                for (int mi = 0; mi < 2; mi++) {
                    int m4[4] = {0, 0, 0, 0};
#pragma unroll
                    for (int kk = 0; kk < 4; kk++)
                        mma_s8(m4, a8[mi][kk], b8[kk][2 * h], b8[kk][2 * h + 1]);
                    acc[mi][ni][0] += (float)m4[0] * SCMID;
                    acc[mi][ni][1] += (float)m4[1] * SCMID;
                    acc[mi][ni][2] += (float)m4[2] * SCMID;
                    acc[mi][ni][3] += (float)m4[3] * SCMID;
                }
            }
        }

        // ---- epilogue: exp + K@alpha into register partials ----
        const float* hxp = (const float*)(sm + SM_HX + bi * 512);
        const char* alp = sm + SM_AL + bi * 10240;
#pragma unroll
        for (int ni = 0; ni < 8; ni++) {
#pragma unroll
            for (int jj = 0; jj < 2; jj++) {
                const int nl = wn * 64 + ni * 8 + (lane & 3) * 2 + jj;
                const float nh = hxp[nl];
                const ulonglong2* ar = (const ulonglong2*)(alp + nl * 80);
                ulonglong2 p0 = ar[0], p1 = ar[1], p2 = ar[2], p3 = ar[3];
#pragma unroll
                for (int mi = 0; mi < 2; mi++) {
                    float e0 = ex2f(acc[mi][ni][jj] - nh);
                    float e1 = ex2f(acc[mi][ni][2 + jj] - nh);
                    ull e20 = pack2(e0), e21 = pack2(e1);
                    ull* o0 = o[2 * mi];
                    ull* o1 = o[2 * mi + 1];
                    fma2(o0[0], e20, p0.x); fma2(o0[1], e20, p0.y);
                    fma2(o0[2], e20, p1.x); fma2(o0[3], e20, p1.y);
                    fma2(o0[4], e20, p2.x); fma2(o0[5], e20, p2.y);
                    fma2(o0[6], e20, p3.x); fma2(o0[7], e20, p3.y);
                    fma2(o1[0], e21, p0.x); fma2(o1[1], e21, p0.y);
                    fma2(o1[2], e21, p1.x); fma2(o1[3], e21, p1.y);
                    fma2(o1[4], e21, p2.x); fma2(o1[5], e21, p2.y);
                    fma2(o1[6], e21, p3.x); fma2(o1[7], e21, p3.y);
                }
            }
        }
        __syncthreads();
        if (j + 2 < tc) {
            load_tile(su, alpha, bi, (chunk + (j + 2) * NCH) * NTL, t, N);
            CP_COMMIT();
        }
    }

    // quad reduction (lanes 4g..4g+3 hold disjoint n slices of same m rows)
    float red[64];
#pragma unroll
    for (int mm = 0; mm < 4; mm++)
#pragma unroll
        for (int fp = 0; fp < 8; fp++) {
            ull v = o[mm][fp];
            float x = __uint_as_float((uint32_t)v);
            float y = __uint_as_float((uint32_t)(v >> 32));
            x += __shfl_xor_sync(0xffffffffu, x, 1);
            x += __shfl_xor_sync(0xffffffffu, x, 2);
            y += __shfl_xor_sync(0xffffffffu, y, 1);
            y += __shfl_xor_sync(0xffffffffu, y, 2);
            red[mm * 16 + fp * 2] = x;
            red[mm * 16 + fp * 2 + 1] = y;
        }
    if ((lane & 3) == 0) {
        const int slab = chunk * 2 + wn;
#pragma unroll
        for (int mm = 0; mm < 4; mm++) {
            int m = mb + wm * 32 + (mm >> 1) * 16 + (mm & 1) * 8 + g8;
            float* pp = g_part + ((size_t)slab * MAXB + m) * FF;
#pragma unroll
            for (int q = 0; q < 4; q++)
                *(float4*)(pp + q * 4) =
                    make_float4(red[mm * 16 + q * 4], red[mm * 16 + q * 4 + 1],
                                red[mm * 16 + q * 4 + 2], red[mm * 16 + q * 4 + 3]);
        }
    }
}

__global__ void reduce_out(float* __restrict__ out, int B) {
    int i = blockIdx.x * blockDim.x + threadIdx.x;
    if (i >= B * FF) return;
    float s = 0.f;
#pragma unroll
    for (int c = 0; c < NSLAB; c++)
        s += g_part[(size_t)c * MAXB * FF + i];
    out[i] = s;
}

extern "C" void kernel_launch(void* const* d_in, const int* in_sizes, int n_in,
                              void* d_out, int out_size) {
    const float* z = (const float*)d_in[0];
    const float* x = (const float*)d_in[1];
    const float* alpha = (const float*)d_in[2];
    int B = in_sizes[0] / DD;   // 2048
    int N = in_sizes[1] / DD;   // 100000

    prep_split<<<(N + B + 255) / 256, 256>>>(z, x, B, N);

    int ntiles = (N + NTL - 1) / NTL;   // 782
    cudaFuncSetAttribute(rbf_main, cudaFuncAttributeMaxDynamicSharedMemorySize,
                         SM_TOT);
    rbf_main<<<dim3(NCH, MBLK), 256, SM_TOT>>>(alpha, N, ntiles);

    reduce_out<<<(B * FF + 255) / 256, 256>>>((float*)d_out, B);
}

// round 17
// speedup vs baseline: 1.4591x; 1.4591x over previous
// RBF regression out[B,F] = exp(-||z-x||^2/2) @ alpha.
// R16 hybrid: R12's 3-pass bf16 HMMA Gram GEMM (tensor-bound, ~96% HMMA
// ceiling) widened to 160-column tiles: columns 128..159 computed on the idle
// fp32 fma pipe (fma.rn.f32x2 SIMT from exact fp32 k-major zT/xT), exp'd to
// smem, and second-GEMM'd by a phase-B pass pipelined one tile late so it
// fills HMMA issue gaps. N = 625*160 exactly. Deterministic slabs + reduce.
#include <cuda_runtime.h>
#include <cuda_bf16.h>
#include <cstdint>

#define DD 64
#define FF 16
#define NTL 160            // 128 tensor + 32 SIMT columns
#define NCH 37
#define MBLK 16
#define NSLAB (NCH * 3)
#define MAXB 2048
#define MAXN 100096
#define XSTR 100096
#define LOG2E 1.4426950408889634f

typedef unsigned long long ull;

__device__ __align__(16) __nv_bfloat16 g_zh[MAXB * DD];
__device__ __align__(16) __nv_bfloat16 g_zl[MAXB * DD];
__device__ __align__(16) __nv_bfloat16 g_xh[(size_t)MAXN * DD];
__device__ __align__(16) __nv_bfloat16 g_xl[(size_t)MAXN * DD];
__device__ __align__(16) float g_zT[DD * MAXB];          // [k][b], *log2e
__device__ __align__(16) float g_xT[(size_t)DD * XSTR];  // [k][n]
__device__ float g_hz[MAXB];
__device__ __align__(16) float g_hx[MAXN];
__device__ __align__(16) float g_part[(size_t)NSLAB * MAXB * FF];

// smem layout (bytes)
#define SM_ZH 0            // 16KB zh tile
#define SM_ZL 16384        // 16KB zl tile
#define SM_ZT 32768        // 32KB zT fp32 [64][128] (512B rows)
#define SM_X  65536        // 2 bufs x 32KB (xh, xl at +16384)
#define SM_XT 131072       // 2 bufs x 8KB   ([64][32] f32, 128B rows)
#define SM_AL 147456       // 2 bufs x 10240 (128 rows x 80B)
#define SM_HX 167936       // 2 bufs x 1024  (160 floats)
#define SM_AS2 169984      // 4 bufs x 2560  (32 rows x 80B)
#define SM_ES 180224       // 2 bufs x 18432 ([128][36] f32, 144B rows)
#define SM_TOT 217088

static __device__ __forceinline__ uint32_t smem_u32(const void* p) {
    uint32_t a;
    asm("{ .reg .u64 t; cvta.to.shared.u64 t, %1; cvt.u32.u64 %0, t; }"
        : "=r"(a) : "l"(p));
    return a;
}
static __device__ __forceinline__ uint32_t swz(uint32_t o) {
    return o ^ ((o >> 3) & 0x70);
}
static __device__ __forceinline__ float ex2f(float x) {
    float y;
    asm("ex2.approx.ftz.f32 %0, %1;" : "=f"(y) : "f"(x));
    return y;
}
static __device__ __forceinline__ ull pack2(float e) {
    ull r;
    asm("mov.b64 %0, {%1, %1};" : "=l"(r) : "f"(e));
    return r;
}
static __device__ __forceinline__ ull packf2(float a, float b) {
    ull r;
    asm("mov.b64 %0, {%1, %2};" : "=l"(r) : "f"(a), "f"(b));
    return r;
}
static __device__ __forceinline__ void unpk(ull v, float& a, float& b) {
    asm("mov.b64 {%0, %1}, %2;" : "=f"(a), "=f"(b) : "l"(v));
}
static __device__ __forceinline__ void fma2(ull& acc, ull a, ull b) {
    asm("fma.rn.f32x2 %0, %1, %2, %0;" : "+l"(acc) : "l"(a), "l"(b));
}
static __device__ __forceinline__ void ldm4(uint32_t a, uint32_t r[4]) {
    asm volatile("ldmatrix.sync.aligned.m8n8.x4.shared.b16 {%0,%1,%2,%3}, [%4];"
                 : "=r"(r[0]), "=r"(r[1]), "=r"(r[2]), "=r"(r[3]) : "r"(a));
}
static __device__ __forceinline__ void mma16816(float c[4], const uint32_t a[4],
                                                const uint32_t b0, const uint32_t b1) {
    asm volatile(
        "mma.sync.aligned.m16n8k16.row.col.f32.bf16.bf16.f32 "
        "{%0,%1,%2,%3}, {%4,%5,%6,%7}, {%8,%9}, {%0,%1,%2,%3};"
        : "+f"(c[0]), "+f"(c[1]), "+f"(c[2]), "+f"(c[3])
        : "r"(a[0]), "r"(a[1]), "r"(a[2]), "r"(a[3]), "r"(b0), "r"(b1));
}
static __device__ __forceinline__ void cpa16(uint32_t dst, const void* src) {
    asm volatile("cp.async.cg.shared.global [%0], [%1], 16;"
                 :: "r"(dst), "l"(src) : "memory");
}
#define CP_COMMIT() asm volatile("cp.async.commit_group;" ::: "memory")
#define CP_WAIT1()  asm volatile("cp.async.wait_group 1;" ::: "memory")
#define CP_WAIT0()  asm volatile("cp.async.wait_group 0;" ::: "memory")

// ---------- prep: bf16 hi/lo splits + fp32 transposes + half-norms ----------
__global__ void prep_split(const float* __restrict__ z,
                           const float* __restrict__ x, int B, int N) {
    int i = blockIdx.x * blockDim.x + threadIdx.x;
    if (i < N) {
        const float4* p = reinterpret_cast<const float4*>(x + (size_t)i * DD);
        float s = 0.f;
#pragma unroll
        for (int q = 0; q < DD / 4; q++) {
            float4 v = p[q];
            s += v.x * v.x + v.y * v.y + v.z * v.z + v.w * v.w;
            float vv[4] = {v.x, v.y, v.z, v.w};
            __nv_bfloat16 h[4], l[4];
#pragma unroll
            for (int e = 0; e < 4; e++) {
                h[e] = __float2bfloat16(vv[e]);
                l[e] = __float2bfloat16(vv[e] - __bfloat162float(h[e]));
                g_xT[(size_t)(q * 4 + e) * XSTR + i] = vv[e];
            }
            *reinterpret_cast<uint2*>(g_xh + (size_t)i * DD + q * 4) =
                *reinterpret_cast<uint2*>(h);
            *reinterpret_cast<uint2*>(g_xl + (size_t)i * DD + q * 4) =
                *reinterpret_cast<uint2*>(l);
        }
        g_hx[i] = 0.5f * s * LOG2E;
    } else if (i < N + B) {
        int b = i - N;
        const float4* p = reinterpret_cast<const float4*>(z + (size_t)b * DD);
        float s = 0.f;
#pragma unroll
        for (int q = 0; q < DD / 4; q++) {
            float4 v = p[q];
            s += v.x * v.x + v.y * v.y + v.z * v.z + v.w * v.w;
            float vv[4] = {v.x * LOG2E, v.y * LOG2E, v.z * LOG2E, v.w * LOG2E};
            __nv_bfloat16 h[4], l[4];
#pragma unroll
            for (int e = 0; e < 4; e++) {
                h[e] = __float2bfloat16(vv[e]);
                l[e] = __float2bfloat16(vv[e] - __bfloat162float(h[e]));
                g_zT[(q * 4 + e) * MAXB + b] = vv[e];
            }
            *reinterpret_cast<uint2*>(g_zh + (size_t)b * DD + q * 4) =
                *reinterpret_cast<uint2*>(h);
            *reinterpret_cast<uint2*>(g_zl + (size_t)b * DD + q * 4) =
                *reinterpret_cast<uint2*>(l);
        }
        g_hz[b] = 0.5f * s * LOG2E;
    }
}

// ---------- per-tile loads (cp.async); nb = tile*160, all in-bounds ----------
static __device__ __forceinline__ void load_tile(uint32_t su, const float* alpha,
                                                 int j, int nb, int t) {
    const int bi = j & 1, b4 = j & 3;
    uint32_t xh_b = su + SM_X + bi * 32768;
    uint32_t xl_b = xh_b + 16384;
#pragma unroll
    for (int r4 = 0; r4 < 4; r4++) {
        int i = t + r4 * 256;
        int r = i >> 3, c = i & 7;
        size_t gi = (size_t)(nb + r) * DD + c * 8;
        cpa16(xh_b + swz(r * 128 + c * 16), g_xh + gi);
        cpa16(xl_b + swz(r * 128 + c * 16), g_xl + gi);
    }
    uint32_t xt_b = su + SM_XT + bi * 8192;
#pragma unroll
    for (int r2 = 0; r2 < 2; r2++) {
        int i = t + r2 * 256;
        int r = i >> 3, c = i & 7;       // r = k row 0..63, c = chunk
        cpa16(xt_b + r * 128 + c * 16,
              g_xT + (size_t)r * XSTR + nb + 128 + c * 4);
    }
    uint32_t al_b = su + SM_AL + bi * 10240;
#pragma unroll
    for (int r2 = 0; r2 < 2; r2++) {
        int i = t + r2 * 256;
        int n = i >> 2, c = i & 3;
        cpa16(al_b + n * 80 + c * 16, alpha + (size_t)(nb + n) * FF + c * 4);
    }
    if (t < 128) {                        // SIMT alpha rows 128..159 (quad buf)
        int n = t >> 2, c = t & 3;
        cpa16(su + SM_AS2 + b4 * 2560 + n * 80 + c * 16,
              alpha + (size_t)(nb + 128 + n) * FF + c * 4);
    }
    if (t < 40)                           // hx: 160 floats
        cpa16(su + SM_HX + bi * 1024 + t * 16, g_hx + nb + t * 4);
}

__global__ __launch_bounds__(256, 1) void rbf_main(
    const float* __restrict__ alpha, int ntiles) {
    extern __shared__ char sm[];
    const uint32_t su = smem_u32(sm);
    const int t = threadIdx.x, lane = t & 31, wid = t >> 5;
    const int wm = wid & 3, wn = wid >> 2;
    const int chunk = blockIdx.x, mb = blockIdx.y * 128;
    const int tc = (ntiles - chunk + NCH - 1) / NCH;
    const int g8 = lane >> 2;
    const int mg = t >> 3, ng = t & 7;    // SIMT-A mapping: 4m x 4n per thread
    const int bb = t >> 1, fh = (t & 1) * 8;  // phase-B mapping

    // z tiles (once): bf16 SW128 + fp32 zT
#pragma unroll
    for (int r4 = 0; r4 < 4; r4++) {
        int i = t + r4 * 256;
        int r = i >> 3, c = i & 7;
        *(uint4*)(sm + SM_ZH + swz(r * 128 + c * 16)) =
            *(const uint4*)(g_zh + (size_t)(mb + r) * DD + c * 8);
        *(uint4*)(sm + SM_ZL + swz(r * 128 + c * 16)) =
            *(const uint4*)(g_zl + (size_t)(mb + r) * DD + c * 8);
    }
#pragma unroll
    for (int r8 = 0; r8 < 8; r8++) {      // zT [64][128] f32: 2048 16B chunks
        int i = t + r8 * 256;
        int r = i >> 5, c = i & 31;
        *(uint4*)(sm + SM_ZT + r * 512 + c * 16) =
            *(const uint4*)(g_zT + (size_t)r * MAXB + mb + c * 4);
    }

    float nhz[4];
#pragma unroll
    for (int mm = 0; mm < 4; mm++)
        nhz[mm] = -g_hz[mb + wm * 32 + (mm >> 1) * 16 + (mm & 1) * 8 + g8];
    float hzm[4];
#pragma unroll
    for (int i = 0; i < 4; i++) hzm[i] = g_hz[mb + mg * 4 + i];

    // ldmatrix lane addressing
    const int lg = lane & 7, sel = lane >> 3;
    const uint32_t xr = (uint32_t)lg << 4;
    const uint32_t a_row = ((sel & 1) << 3) + lg;
    const uint32_t a_kx = (uint32_t)(sel >> 1) << 4;
    const uint32_t b_row = ((sel >> 1) << 3) + lg;
    const uint32_t b_kx = (uint32_t)(sel & 1) << 4;
    uint32_t abase_h[2], abase_l[2];
#pragma unroll
    for (int mi = 0; mi < 2; mi++) {
        uint32_t ro = (wm * 32 + mi * 16 + a_row) * 128;
        abase_h[mi] = su + SM_ZH + ro;
        abase_l[mi] = su + SM_ZL + ro;
    }

    ull o[4][8];
#pragma unroll
    for (int mm = 0; mm < 4; mm++)
#pragma unroll
        for (int fp = 0; fp < 8; fp++) o[mm][fp] = 0ull;
    ull oacc2[4] = {0ull, 0ull, 0ull, 0ull};

    load_tile(su, alpha, 0, chunk * NTL, t);
    CP_COMMIT();
    if (tc > 1) load_tile(su, alpha, 1, (chunk + NCH) * NTL, t);
    CP_COMMIT();

    for (int j = 0; j < tc; j++) {
        const int bi = j & 1, b4p = (j - 1) & 3;
        if (j + 1 < tc) CP_WAIT1(); else CP_WAIT0();
        __syncthreads();

        float acc[2][8][4];
#pragma unroll
        for (int mi = 0; mi < 2; mi++)
#pragma unroll
            for (int ni = 0; ni < 8; ni++) {
                acc[mi][ni][0] = nhz[2 * mi];
                acc[mi][ni][1] = nhz[2 * mi];
                acc[mi][ni][2] = nhz[2 * mi + 1];
                acc[mi][ni][3] = nhz[2 * mi + 1];
            }
        ull sacc[4][2];
#pragma unroll
        for (int i = 0; i < 4; i++) { sacc[i][0] = 0ull; sacc[i][1] = 0ull; }

        const uint32_t xh_b = su + SM_X + bi * 32768;
        const uint32_t xl_b = xh_b + 16384;
        const uint32_t xt_b = su + SM_XT + bi * 8192;
        const uint32_t es_r = su + SM_ES + (1 - bi) * 18432;  // prev es
        const uint32_t as2_r = su + SM_AS2 + b4p * 2560;      // prev SIMT alpha
        uint32_t bbase_h[4], bbase_l[4];
#pragma unroll
        for (int q = 0; q < 4; q++) {
            uint32_t ro = (wn * 64 + q * 16 + b_row) * 128;
            bbase_h[q] = xh_b + ro;
            bbase_l[q] = xl_b + ro;
        }

#pragma unroll
        for (int ks = 0; ks < 4; ks++) {
            // --- tensor: 48 HMMA for this kstep ---
            const uint32_t kxa = ((uint32_t)(ks * 32) + a_kx) ^ xr;
            const uint32_t kxb = ((uint32_t)(ks * 32) + b_kx) ^ xr;
            uint32_t ah[2][4], al[2][4];
            ldm4(abase_h[0] + kxa, ah[0]);
            ldm4(abase_h[1] + kxa, ah[1]);
            ldm4(abase_l[0] + kxa, al[0]);
            ldm4(abase_l[1] + kxa, al[1]);
#pragma unroll
            for (int q = 0; q < 4; q++) {
                uint32_t bh4[4], bl4[4];
                ldm4(bbase_h[q] + kxb, bh4);
                ldm4(bbase_l[q] + kxb, bl4);
#pragma unroll
                for (int h = 0; h < 2; h++) {
                    const int ni = 2 * q + h;
#pragma unroll
                    for (int mi = 0; mi < 2; mi++) {
                        mma16816(acc[mi][ni], ah[mi], bh4[2 * h], bh4[2 * h + 1]);
                        mma16816(acc[mi][ni], ah[mi], bl4[2 * h], bl4[2 * h + 1]);
                        mma16816(acc[mi][ni], al[mi], bh4[2 * h], bh4[2 * h + 1]);
                    }
                }
            }
            // --- SIMT-A: fp32 k-chunk (fills HMMA issue gaps) ---
#pragma unroll
            for (int kk = 0; kk < 16; kk++) {
                const int k = ks * 16 + kk;
                float4 a4 = *(const float4*)(sm + SM_ZT + k * 512 + mg * 16);
                float4 b4v = *(const float4*)(sm + (xt_b - su) + k * 128 + ng * 16);
                ull b01 = packf2(b4v.x, b4v.y), b23 = packf2(b4v.z, b4v.w);
                float av[4] = {a4.x, a4.y, a4.z, a4.w};
#pragma unroll
                for (int i = 0; i < 4; i++) {
                    ull ad = pack2(av[i]);
                    fma2(sacc[i][0], ad, b01);
                    fma2(sacc[i][1], ad, b23);
                }
            }
            // --- phase-B chunk for previous tile (8 n per ks) ---
            if (j > 0) {
#pragma unroll
                for (int nq = 0; nq < 2; nq++) {
                    const int n4 = ks * 2 + nq;
                    float4 e4 = *(const float4*)(sm + (es_r - su) + bb * 144 + n4 * 16);
                    float ev[4] = {e4.x, e4.y, e4.z, e4.w};
#pragma unroll
                    for (int jj = 0; jj < 4; jj++) {
                        const ulonglong2* ar = (const ulonglong2*)(
                            sm + (as2_r - su) + (n4 * 4 + jj) * 80 + fh * 4);
                        ulonglong2 p0 = ar[0], p1 = ar[1];
                        ull e2 = pack2(ev[jj]);
                        fma2(oacc2[0], e2, p0.x); fma2(oacc2[1], e2, p0.y);
                        fma2(oacc2[2], e2, p1.x); fma2(oacc2[3], e2, p1.y);
                    }
                }
            }
        }

        // --- SIMT exp + stage es(bi) ---
        {
            const float* hxp = (const float*)(sm + SM_HX + bi * 1024);
            float4 hx4 = *(const float4*)(hxp + 128 + ng * 4);
            uint32_t es_w = su + SM_ES + bi * 18432;
#pragma unroll
            for (int i = 0; i < 4; i++) {
                float v0, v1, v2, v3;
                unpk(sacc[i][0], v0, v1);
                unpk(sacc[i][1], v2, v3);
                float4 ev;
                ev.x = ex2f(v0 - hzm[i] - hx4.x);
                ev.y = ex2f(v1 - hzm[i] - hx4.y);
                ev.z = ex2f(v2 - hzm[i] - hx4.z);
                ev.w = ex2f(v3 - hzm[i] - hx4.w);
                *(float4*)(sm + (es_w - su) + (mg * 4 + i) * 144 + ng * 16) = ev;
            }
        }

        // --- tensor epilogue: exp + K@alpha into register partials ---
        {
            const float* hxp = (const float*)(sm + SM_HX + bi * 1024);
            const char* alp = sm + SM_AL + bi * 10240;
#pragma unroll
            for (int ni = 0; ni < 8; ni++) {
#pragma unroll
                for (int jj = 0; jj < 2; jj++) {
                    const int nl = wn * 64 + ni * 8 + (lane & 3) * 2 + jj;
                    const float nh = hxp[nl];
                    const ulonglong2* ar = (const ulonglong2*)(alp + nl * 80);
                    ulonglong2 p0 = ar[0], p1 = ar[1], p2 = ar[2], p3 = ar[3];
#pragma unroll
                    for (int mi = 0; mi < 2; mi++) {
                        float e0 = ex2f(acc[mi][ni][jj] - nh);
                        float e1 = ex2f(acc[mi][ni][2 + jj] - nh);
                        ull e20 = pack2(e0), e21 = pack2(e1);
                        ull* o0 = o[2 * mi];
                        ull* o1 = o[2 * mi + 1];
                        fma2(o0[0], e20, p0.x); fma2(o0[1], e20, p0.y);
                        fma2(o0[2], e20, p1.x); fma2(o0[3], e20, p1.y);
                        fma2(o0[4], e20, p2.x); fma2(o0[5], e20, p2.y);
                        fma2(o0[6], e20, p3.x); fma2(o0[7], e20, p3.y);
                        fma2(o1[0], e21, p0.x); fma2(o1[1], e21, p0.y);
                        fma2(o1[2], e21, p1.x); fma2(o1[3], e21, p1.y);
                        fma2(o1[4], e21, p2.x); fma2(o1[5], e21, p2.y);
                        fma2(o1[6], e21, p3.x); fma2(o1[7], e21, p3.y);
                    }
                }
            }
        }
        __syncthreads();
        if (j + 2 < tc) {
            load_tile(su, alpha, j + 2, (chunk + (j + 2) * NCH) * NTL, t);
            CP_COMMIT();
        }
    }

    // --- final phase-B for last tile ---
    {
        const int jl = tc - 1;
        const uint32_t es_r = su + SM_ES + (jl & 1) * 18432;
        const uint32_t as2_r = su + SM_AS2 + (jl & 3) * 2560;
#pragma unroll
        for (int n4 = 0; n4 < 8; n4++) {
            float4 e4 = *(const float4*)(sm + (es_r - su) + bb * 144 + n4 * 16);
            float ev[4] = {e4.x, e4.y, e4.z, e4.w};
#pragma unroll
            for (int jj = 0; jj < 4; jj++) {
                const ulonglong2* ar = (const ulonglong2*)(
                    sm + (as2_r - su) + (n4 * 4 + jj) * 80 + fh * 4);
                ulonglong2 p0 = ar[0], p1 = ar[1];
                ull e2 = pack2(ev[jj]);
                fma2(oacc2[0], e2, p0.x); fma2(oacc2[1], e2, p0.y);
                fma2(oacc2[2], e2, p1.x); fma2(oacc2[3], e2, p1.y);
            }
        }
    }

    // tensor quad reduction + slab write
    float red[64];
#pragma unroll
    for (int mm = 0; mm < 4; mm++)
#pragma unroll
        for (int fp = 0; fp < 8; fp++) {
            ull v = o[mm][fp];
            float x = __uint_as_float((uint32_t)v);
            float y = __uint_as_float((uint32_t)(v >> 32));
            x += __shfl_xor_sync(0xffffffffu, x, 1);
            x += __shfl_xor_sync(0xffffffffu, x, 2);
            y += __shfl_xor_sync(0xffffffffu, y, 1);
            y += __shfl_xor_sync(0xffffffffu, y, 2);
            red[mm * 16 + fp * 2] = x;
            red[mm * 16 + fp * 2 + 1] = y;
        }
    if ((lane & 3) == 0) {
        const int slab = chunk * 2 + wn;
#pragma unroll
        for (int mm = 0; mm < 4; mm++) {
            int m = mb + wm * 32 + (mm >> 1) * 16 + (mm & 1) * 8 + g8;
            float* pp = g_part + ((size_t)slab * MAXB + m) * FF;
#pragma unroll
            for (int q = 0; q < 4; q++)
                *(float4*)(pp + q * 4) =
                    make_float4(red[mm * 16 + q * 4], red[mm * 16 + q * 4 + 1],
                                red[mm * 16 + q * 4 + 2], red[mm * 16 + q * 4 + 3]);
        }
    }
    // SIMT slab write (thread owns (m=bb, f half))
    {
        float v[8];
        unpk(oacc2[0], v[0], v[1]);
        unpk(oacc2[1], v[2], v[3]);
        unpk(oacc2[2], v[4], v[5]);
        unpk(oacc2[3], v[6], v[7]);
        float* pp = g_part + ((size_t)(2 * NCH + chunk) * MAXB + mb + bb) * FF + fh;
        *(float4*)(pp + 0) = make_float4(v[0], v[1], v[2], v[3]);
        *(float4*)(pp + 4) = make_float4(v[4], v[5], v[6], v[7]);
    }
}

__global__ void reduce_out(float* __restrict__ out, int B) {
    int i = blockIdx.x * blockDim.x + threadIdx.x;
    if (i >= B * FF) return;
    float s = 0.f;
#pragma unroll
    for (int c = 0; c < NSLAB; c++)
        s += g_part[(size_t)c * MAXB * FF + i];
    out[i] = s;
}

extern "C" void kernel_launch(void* const* d_in, const int* in_sizes, int n_in,
                              void* d_out, int out_size) {
    const float* z = (const float*)d_in[0];
    const float* x = (const float*)d_in[1];
    const float* alpha = (const float*)d_in[2];
    int B = in_sizes[0] / DD;   // 2048
    int N = in_sizes[1] / DD;   // 100000

    prep_split<<<(N + B + 255) / 256, 256>>>(z, x, B, N);

    int ntiles = (N + NTL - 1) / NTL;   // 625 exactly
    cudaFuncSetAttribute(rbf_main, cudaFuncAttributeMaxDynamicSharedMemorySize,
                         SM_TOT);
    rbf_main<<<dim3(NCH, MBLK), 256, SM_TOT>>>(alpha, ntiles);

    reduce_out<<<(B * FF + 255) / 256, 256>>>((float*)d_out, B);
}